// round 1
// baseline (speedup 1.0000x reference)
#include <cuda_runtime.h>

// ---------------------------------------------------------------------------
// HiggsAudioModel merge: scatter text + audio-code embeddings into a merged,
// left-padded sequence. Shapes fixed by the problem instance:
//   B=8, S=2048, D=2048, M=4088, n_in=n_out=32 placeholders, L=256 codes each.
// Output: concat([final_embedding (B,M,D), attention (B,M), labels (B,M),
//                 position_ids (B,M), input_ids (B,M), in_fill, in_discrete,
//                 out_fill]) as float32.
// ---------------------------------------------------------------------------

#define TOK_IN   128011
#define TOK_OUT  128012
#define TOK_PAD  128001
#define LBL_IGN  (-100)

static constexpr int B_ = 8;
static constexpr int S_ = 2048;
static constexpr int D_ = 2048;
static constexpr int M_ = 4088;
static constexpr int MAXP = 64;   // max placeholders per type (actual 32)

// ------------------------- scratch (device globals) ------------------------
__device__ int g_new_pos[B_ * S_];     // merged column of each original slot
__device__ int g_src[B_ * M_];         // per merged row: source row id or -1
__device__ int g_cnt_in[B_], g_cnt_out[B_];
__device__ int g_base_in[B_], g_base_out[B_];
__device__ int g_in_len[MAXP], g_out_len[MAXP];
__device__ int g_seg_b_in[MAXP],  g_seg_end_in[MAXP];
__device__ int g_seg_b_out[MAXP], g_seg_end_out[MAXP];

// ------------------------------- kernels -----------------------------------

// K0: defaults for metadata outputs + src map
__global__ void k_init(float* __restrict__ out) {
    int i = blockIdx.x * blockDim.x + threadIdx.x;
    if (i >= B_ * M_) return;
    g_src[i] = -1;
    const size_t BM = (size_t)B_ * M_;
    float* meta = out + (size_t)B_ * M_ * D_;
    meta[i]           = 0.0f;             // attention
    meta[BM + i]      = (float)LBL_IGN;   // labels
    // position_ids (2*BM) fully written by k_pos
    meta[3 * BM + i]  = (float)TOK_PAD;   // input_ids
    meta[4 * BM + i]  = 0.0f;             // in_fill
    meta[5 * BM + i]  = 0.0f;             // in_discrete
    meta[6 * BM + i]  = 0.0f;             // out_fill
}

// K1a: per-row placeholder counts
__global__ void k_count(const int* __restrict__ ids) {
    int b = blockIdx.x, t = threadIdx.x;
    int cin = 0, cout = 0;
    for (int s = t; s < S_; s += 256) {
        int id = ids[b * S_ + s];
        cin  += (id == TOK_IN);
        cout += (id == TOK_OUT);
    }
    __shared__ int s1[256], s2[256];
    s1[t] = cin; s2[t] = cout;
    __syncthreads();
    if (t == 0) {
        int a = 0, c = 0;
        for (int i = 0; i < 256; i++) { a += s1[i]; c += s2[i]; }
        g_cnt_in[b] = a; g_cnt_out[b] = c;
    }
}

// K1b: cross-row exclusive prefix + code lengths from starts
__global__ void k_prefix(const int* __restrict__ in_starts,
                         const int* __restrict__ out_starts,
                         int n_in, int n_out, int tot_in, int tot_out) {
    int p = threadIdx.x;
    if (p == 0) {
        int a = 0;
        for (int b = 0; b < B_; b++) { g_base_in[b] = a;  a += g_cnt_in[b]; }
        a = 0;
        for (int b = 0; b < B_; b++) { g_base_out[b] = a; a += g_cnt_out[b]; }
    }
    if (p < n_in)
        g_in_len[p]  = ((p + 1 < n_in)  ? in_starts[p + 1]  : tot_in)  - in_starts[p];
    if (p < n_out)
        g_out_len[p] = ((p + 1 < n_out) ? out_starts[p + 1] : tot_out) - out_starts[p];
}

// K1c: per-row scan of tokens-per-slot -> merged columns + segment records
__global__ void k_scan_rows(const int* __restrict__ ids_g) {
    int b = blockIdx.x, t = threadIdx.x;          // 256 threads, 8 elems each
    const int* row = ids_g + b * S_;
    __shared__ int sh_in[257], sh_out[257], sh_tpn[257];

    int ids[8];
    int cin = 0, cout = 0;
    #pragma unroll
    for (int i = 0; i < 8; i++) {
        int id = row[t * 8 + i];
        ids[i] = id;
        cin  += (id == TOK_IN);
        cout += (id == TOK_OUT);
    }
    sh_in[t] = cin; sh_out[t] = cout;
    __syncthreads();
    if (t == 0) {
        int a = 0, c = 0;
        for (int i = 0; i < 256; i++) {
            int x = sh_in[i];  sh_in[i]  = a; a += x;
            int y = sh_out[i]; sh_out[i] = c; c += y;
        }
        sh_in[256] = a; sh_out[256] = c;
    }
    __syncthreads();

    int rank_in  = g_base_in[b]  + sh_in[t];   // global ordinal of first in-ph in chunk
    int rank_out = g_base_out[b] + sh_out[t];

    // tokens-per-slot sum for this chunk (placeholder -> its code length)
    int tsum = 0;
    {
        int ri = rank_in, ro = rank_out;
        #pragma unroll
        for (int i = 0; i < 8; i++) {
            int id = ids[i];
            int v = 1;
            if (id == TOK_IN)  v = g_in_len[ri++];
            else if (id == TOK_OUT) v = g_out_len[ro++];
            tsum += v;
        }
    }
    sh_tpn[t] = tsum;
    __syncthreads();
    if (t == 0) {
        int a = 0;
        for (int i = 0; i < 256; i++) { int x = sh_tpn[i]; sh_tpn[i] = a; a += x; }
        sh_tpn[256] = a;
    }
    __syncthreads();

    int shift = M_ - sh_tpn[256];   // left-pad shift (cum-1+shift with shift=M-total... folded)
    int cum = sh_tpn[t];
    int ri = rank_in, ro = rank_out;
    #pragma unroll
    for (int i = 0; i < 8; i++) {
        int id = ids[i];
        int v = 1;
        if (id == TOK_IN)  v = g_in_len[ri];
        else if (id == TOK_OUT) v = g_out_len[ro];
        cum += v;
        int np = cum - 1 + shift;
        g_new_pos[b * S_ + t * 8 + i] = np;
        if (id == TOK_IN)  { g_seg_b_in[ri]  = b; g_seg_end_in[ri]  = np; ri++; }
        else if (id == TOK_OUT) { g_seg_b_out[ro] = b; g_seg_end_out[ro] = np; ro++; }
    }
}

// K3: scatter text metadata + src map
__global__ void k_text(const int* __restrict__ ids,
                       const int* __restrict__ labels,
                       const int* __restrict__ amask,
                       float* __restrict__ out) {
    int i = blockIdx.x * blockDim.x + threadIdx.x;
    if (i >= B_ * S_) return;
    int id = ids[i];
    if (id == TOK_IN || id == TOK_OUT) return;
    int b = i / S_;
    int o = b * M_ + g_new_pos[i];
    g_src[o] = i;
    const size_t BM = (size_t)B_ * M_;
    float* meta = out + (size_t)B_ * M_ * D_;
    meta[o]          = (float)amask[i];
    meta[BM + o]     = (float)labels[i];
    meta[3 * BM + o] = (float)id;
}

// K4: scatter audio metadata + src map (one thread per code row)
__global__ void k_audio(const int* __restrict__ in_starts,
                        const int* __restrict__ out_starts,
                        int n_in, int n_out, int tot_in, int tot_out,
                        float* __restrict__ out) {
    int i = blockIdx.x * blockDim.x + threadIdx.x;
    if (i >= tot_in + tot_out) return;
    bool isin = (i < tot_in);
    int r = isin ? i : i - tot_in;
    const int* st = isin ? in_starts : out_starts;
    int n = isin ? n_in : n_out;
    // searchsorted(right) - 1
    int lo = 0, hi = n;
    while (lo < hi) { int mid = (lo + hi) >> 1; if (st[mid] <= r) lo = mid + 1; else hi = mid; }
    int p = lo - 1;
    int len = isin ? g_in_len[p]     : g_out_len[p];
    int end = isin ? g_seg_end_in[p] : g_seg_end_out[p];
    int b   = isin ? g_seg_b_in[p]   : g_seg_b_out[p];
    int c = end - len + 1 + (r - st[p]);
    int o = b * M_ + c;
    g_src[o] = B_ * S_ + i;            // combined audio row index
    const size_t BM = (size_t)B_ * M_;
    float* meta = out + (size_t)B_ * M_ * D_;
    meta[o]          = 1.0f;                                   // attention
    meta[3 * BM + o] = (float)(isin ? TOK_IN : TOK_OUT);       // input_ids
    if (isin) { meta[4 * BM + o] = 1.0f; meta[5 * BM + o] = 1.0f; }
    else      { meta[6 * BM + o] = 1.0f; }
}

// K5: position_ids = cumsum(attention)-1, 1 where attention==0
__global__ void k_pos(float* __restrict__ out) {
    int b = blockIdx.x, t = threadIdx.x;     // 256 threads, 16 elems each
    const size_t BM = (size_t)B_ * M_;
    const float* attn = out + (size_t)B_ * M_ * D_ + (size_t)b * M_;
    float* pos = out + (size_t)B_ * M_ * D_ + 2 * BM + (size_t)b * M_;
    __shared__ int sh[256];
    int base = t * 16;
    int a[16], s = 0;
    #pragma unroll
    for (int i = 0; i < 16; i++) {
        int idx = base + i;
        int v = (idx < M_) ? (int)attn[idx] : 0;
        a[i] = v; s += v;
    }
    sh[t] = s;
    __syncthreads();
    if (t == 0) {
        int acc = 0;
        for (int i = 0; i < 256; i++) { int x = sh[i]; sh[i] = acc; acc += x; }
    }
    __syncthreads();
    int cum = sh[t];
    #pragma unroll
    for (int i = 0; i < 16; i++) {
        int idx = base + i;
        if (idx >= M_) break;
        cum += a[i];
        pos[idx] = (float)((a[i] == 0) ? 1 : (cum - 1));
    }
}

// K6: the heavy gather — one CTA per merged row, float4 copies
__global__ void __launch_bounds__(256) k_copy(const float4* __restrict__ in_e,
                                              const float4* __restrict__ out_e,
                                              const float4* __restrict__ txt_e,
                                              int tot_in,
                                              float4* __restrict__ dst_all) {
    int row = blockIdx.x;
    int si = g_src[row];
    float4* dst = dst_all + (size_t)row * (D_ / 4);
    int t = threadIdx.x;
    if (si < 0) {
        float4 z = make_float4(0.f, 0.f, 0.f, 0.f);
        dst[t] = z; dst[t + 256] = z;
        return;
    }
    const float4* src;
    if (si < B_ * S_) {
        src = txt_e + (size_t)si * (D_ / 4);
    } else {
        int r = si - B_ * S_;
        src = (r < tot_in) ? in_e + (size_t)r * (D_ / 4)
                           : out_e + (size_t)(r - tot_in) * (D_ / 4);
    }
    dst[t]       = src[t];
    dst[t + 256] = src[t + 256];
}

// ------------------------------- launcher ----------------------------------
extern "C" void kernel_launch(void* const* d_in, const int* in_sizes, int n_in_args,
                              void* d_out, int out_size) {
    const float* a_in_e  = (const float*)d_in[0];
    const float* a_out_e = (const float*)d_in[1];
    const float* txt_e   = (const float*)d_in[2];
    const int* in_starts  = (const int*)d_in[3];
    const int* out_starts = (const int*)d_in[4];
    const int* ids    = (const int*)d_in[5];
    const int* amask  = (const int*)d_in[6];
    const int* labels = (const int*)d_in[7];

    const int tot_in  = in_sizes[0] / D_;   // audio-in embed rows
    const int tot_out = in_sizes[1] / D_;
    const int n_in  = in_sizes[3];
    const int n_out = in_sizes[4];

    float* out = (float*)d_out;

    k_init<<<(B_ * M_ + 255) / 256, 256>>>(out);
    k_count<<<B_, 256>>>(ids);
    k_prefix<<<1, 64>>>(in_starts, out_starts, n_in, n_out, tot_in, tot_out);
    k_scan_rows<<<B_, 256>>>(ids);
    k_text<<<(B_ * S_ + 255) / 256, 256>>>(ids, labels, amask, out);
    k_audio<<<(tot_in + tot_out + 255) / 256, 256>>>(in_starts, out_starts,
                                                     n_in, n_out, tot_in, tot_out, out);
    k_pos<<<B_, 256>>>(out);
    k_copy<<<B_ * M_, 256>>>((const float4*)a_in_e, (const float4*)a_out_e,
                             (const float4*)txt_e, tot_in, (float4*)out);
}

// round 2
// speedup vs baseline: 1.0238x; 1.0238x over previous
#include <cuda_runtime.h>

// ---------------------------------------------------------------------------
// HiggsAudioModel merge — R2: fused prologue (warp-shuffle scans, 1 CTA),
// inverted metadata gather, streaming-hint bulk copy.
//   B=8, S=2048, D=2048, M=4088. Output = concat(embedding, 7 meta arrays) f32.
// ---------------------------------------------------------------------------

#define TOK_IN   128011
#define TOK_OUT  128012
#define TOK_PAD  128001
#define LBL_IGN  (-100)

static constexpr int B_ = 8, S_ = 2048, D_ = 2048, M_ = 4088, MAXP = 64;
static constexpr int BS_ = B_ * S_;
static constexpr int BM_ = B_ * M_;

// per merged position: text row (0..BS_-1), BS_+audio row, or -1 (pad)
__device__ int g_src[BM_];

__device__ __forceinline__ int wscan_incl(int v) {
    int lane = threadIdx.x & 31;
    #pragma unroll
    for (int o = 1; o < 32; o <<= 1) {
        int n = __shfl_up_sync(0xffffffffu, v, o);
        if (lane >= o) v += n;
    }
    return v;
}

// ---- A: full setup in one CTA (1024 threads, 16 ids per thread) ------------
__global__ void __launch_bounds__(1024) k_setup(
        const int* __restrict__ ids_g,
        const int* __restrict__ in_starts, const int* __restrict__ out_starts,
        int n_in, int n_out, int tot_in, int tot_out) {
    __shared__ int s_in_len[MAXP], s_out_len[MAXP];
    __shared__ int s_in_st[MAXP], s_out_st[MAXP];
    __shared__ int s_w_in[32], s_w_out[32], s_w_tpn[32];
    __shared__ int s_seg_b[2 * MAXP], s_seg_end[2 * MAXP];  // [0,MAXP)=in

    int tid = threadIdx.x;
    int lane = tid & 31, warp = tid >> 5;
    int b = tid >> 7;                       // 128 threads per row

    if (tid < n_in) {
        int st = in_starts[tid];
        s_in_st[tid] = st;
        s_in_len[tid] = ((tid + 1 < n_in) ? in_starts[tid + 1] : tot_in) - st;
    }
    if (tid < n_out) {
        int st = out_starts[tid];
        s_out_st[tid] = st;
        s_out_len[tid] = ((tid + 1 < n_out) ? out_starts[tid + 1] : tot_out) - st;
    }
    // init g_src = -1 (vectorized; BM_ divisible by 4)
    {
        int4* p = (int4*)g_src;
        int4 mm = make_int4(-1, -1, -1, -1);
        for (int i = tid; i < BM_ / 4; i += 1024) p[i] = mm;
    }
    // load this thread's 16 ids
    int idl[16];
    {
        const int4* p = (const int4*)(ids_g + tid * 16);
        #pragma unroll
        for (int j = 0; j < 4; j++) {
            int4 v = p[j];
            idl[4*j+0] = v.x; idl[4*j+1] = v.y; idl[4*j+2] = v.z; idl[4*j+3] = v.w;
        }
    }
    int cin = 0, cout = 0;
    #pragma unroll
    for (int j = 0; j < 16; j++) { cin += (idl[j] == TOK_IN); cout += (idl[j] == TOK_OUT); }

    // global (cross-row, row-major) exclusive scan of placeholder counts
    int sin = wscan_incl(cin), sout = wscan_incl(cout);
    if (lane == 31) { s_w_in[warp] = sin; s_w_out[warp] = sout; }
    __syncthreads();
    if (warp == 0) {
        int vi = s_w_in[lane], vo = s_w_out[lane];
        int si = wscan_incl(vi), so = wscan_incl(vo);
        s_w_in[lane] = si - vi;             // exclusive warp offsets
        s_w_out[lane] = so - vo;
    }
    __syncthreads();
    int rank_in  = s_w_in[warp]  + sin  - cin;   // global ordinal of my first IN
    int rank_out = s_w_out[warp] + sout - cout;

    // tokens-per-slot chunk sum (placeholder -> code length)
    int tsum = 0;
    {
        int ri = rank_in, ro = rank_out;
        #pragma unroll
        for (int j = 0; j < 16; j++) {
            int id = idl[j];
            int v = 1;
            if (id == TOK_IN)       v = s_in_len[ri++];
            else if (id == TOK_OUT) v = s_out_len[ro++];
            tsum += v;
        }
    }
    // segmented (per-row) scan: 4 warps per row
    int stpn = wscan_incl(tsum);
    if (lane == 31) s_w_tpn[warp] = stpn;
    __syncthreads();
    int wir = warp & 3, wbase = warp & ~3;
    int excl = 0, rowtot = 0;
    #pragma unroll
    for (int w = 0; w < 4; w++) {
        int v = s_w_tpn[wbase + w];
        if (w < wir) excl += v;
        rowtot += v;
    }
    int shift = M_ - rowtot;                // left-pad shift
    int cum = excl + stpn - tsum;           // exclusive prefix within row
    {
        int ri = rank_in, ro = rank_out;
        #pragma unroll
        for (int j = 0; j < 16; j++) {
            int id = idl[j];
            int v = 1;
            if (id == TOK_IN)       v = s_in_len[ri];
            else if (id == TOK_OUT) v = s_out_len[ro];
            cum += v;
            int np = cum - 1 + shift;       // merged column of this slot
            if (id == TOK_IN)       { s_seg_b[ri] = b;        s_seg_end[ri] = np;        ri++; }
            else if (id == TOK_OUT) { s_seg_b[MAXP+ro] = b;   s_seg_end[MAXP+ro] = np;   ro++; }
            else                    g_src[b * M_ + np] = tid * 16 + j;   // text
        }
    }
    __syncthreads();
    // map each audio code row -> merged position
    int total = tot_in + tot_out;
    for (int i = tid; i < total; i += 1024) {
        bool isin = i < tot_in;
        int r = isin ? i : i - tot_in;
        const int* st = isin ? s_in_st : s_out_st;
        int n = isin ? n_in : n_out;
        int lo = 0, hi = n;                 // searchsorted(right)-1
        while (lo < hi) { int mid = (lo + hi) >> 1; if (st[mid] <= r) lo = mid + 1; else hi = mid; }
        int p = lo - 1;
        int len = isin ? s_in_len[p]  : s_out_len[p];
        int end = isin ? s_seg_end[p] : s_seg_end[MAXP + p];
        int bb  = isin ? s_seg_b[p]   : s_seg_b[MAXP + p];
        int c = end - len + 1 + (r - st[p]);
        g_src[bb * M_ + c] = BS_ + i;
    }
}

// ---- B: all scalar metadata, gathered per output position ------------------
__global__ void k_meta(const int* __restrict__ ids, const int* __restrict__ labels,
                       const int* __restrict__ amask, int tot_in,
                       float* __restrict__ out) {
    int i = blockIdx.x * 256 + threadIdx.x;
    if (i >= BM_) return;
    int si = g_src[i];
    float attn, lbl, iid, fin = 0.f, find = 0.f, fout = 0.f;
    if (si < 0)        { attn = 0.f; lbl = (float)LBL_IGN; iid = (float)TOK_PAD; }
    else if (si < BS_) { attn = (float)amask[si]; lbl = (float)labels[si]; iid = (float)ids[si]; }
    else {
        attn = 1.f; lbl = (float)LBL_IGN;
        int r = si - BS_;
        if (r < tot_in) { iid = (float)TOK_IN;  fin = 1.f; find = 1.f; }
        else            { iid = (float)TOK_OUT; fout = 1.f; }
    }
    float* meta = out + (size_t)BM_ * D_;
    const size_t BM = (size_t)BM_;
    meta[i]          = attn;
    meta[BM + i]     = lbl;
    meta[3 * BM + i] = iid;
    meta[4 * BM + i] = fin;
    meta[5 * BM + i] = find;
    meta[6 * BM + i] = fout;
}

// ---- C: position_ids = cumsum(attention)-1 (1 where attn==0), warp scans ---
__global__ void __launch_bounds__(256) k_pos(float* __restrict__ out) {
    int bb = blockIdx.x, t = threadIdx.x;   // 256 threads, 16 elems each
    int lane = t & 31, warp = t >> 5;       // 8 warps
    const size_t BM = (size_t)BM_;
    const float* attn = out + (size_t)BM_ * D_ + (size_t)bb * M_;
    float* pos = out + (size_t)BM_ * D_ + 2 * BM + (size_t)bb * M_;
    __shared__ int s_w[8];
    int base = t * 16;
    int a[16], s = 0;
    #pragma unroll
    for (int j = 0; j < 16; j++) {
        int idx = base + j;
        int v = (idx < M_) ? (int)attn[idx] : 0;
        a[j] = v; s += v;
    }
    int sc = wscan_incl(s);
    if (lane == 31) s_w[warp] = sc;
    __syncthreads();
    int excl = 0;
    #pragma unroll
    for (int w = 0; w < 8; w++) if (w < warp) excl += s_w[w];
    int cum = excl + sc - s;
    #pragma unroll
    for (int j = 0; j < 16; j++) {
        int idx = base + j;
        if (idx >= M_) break;
        cum += a[j];
        pos[idx] = (float)((a[j] == 0) ? 1 : (cum - 1));
    }
}

// ---- D: heavy row gather (one CTA per merged row, streaming hints) ---------
__global__ void __launch_bounds__(256) k_copy(const float4* __restrict__ in_e,
                                              const float4* __restrict__ out_e,
                                              const float4* __restrict__ txt_e,
                                              int tot_in,
                                              float4* __restrict__ dst_all) {
    int row = blockIdx.x;
    int si = g_src[row];
    float4* dst = dst_all + (size_t)row * (D_ / 4);
    int t = threadIdx.x;
    if (si < 0) {
        float4 z = make_float4(0.f, 0.f, 0.f, 0.f);
        __stcs(dst + t, z);
        __stcs(dst + t + 256, z);
        return;
    }
    const float4* src;
    if (si < BS_) src = txt_e + (size_t)si * (D_ / 4);
    else {
        int r = si - BS_;
        src = (r < tot_in) ? in_e + (size_t)r * (D_ / 4)
                           : out_e + (size_t)(r - tot_in) * (D_ / 4);
    }
    float4 v0 = __ldcs(src + t);
    float4 v1 = __ldcs(src + t + 256);
    __stcs(dst + t, v0);
    __stcs(dst + t + 256, v1);
}

// ------------------------------- launcher ----------------------------------
extern "C" void kernel_launch(void* const* d_in, const int* in_sizes, int n_in_args,
                              void* d_out, int out_size) {
    const float* a_in_e  = (const float*)d_in[0];
    const float* a_out_e = (const float*)d_in[1];
    const float* txt_e   = (const float*)d_in[2];
    const int* in_starts  = (const int*)d_in[3];
    const int* out_starts = (const int*)d_in[4];
    const int* ids    = (const int*)d_in[5];
    const int* amask  = (const int*)d_in[6];
    const int* labels = (const int*)d_in[7];

    const int tot_in  = in_sizes[0] / D_;
    const int tot_out = in_sizes[1] / D_;
    const int n_in  = in_sizes[3];
    const int n_out = in_sizes[4];

    float* out = (float*)d_out;

    k_setup<<<1, 1024>>>(ids, in_starts, out_starts, n_in, n_out, tot_in, tot_out);
    k_copy<<<BM_, 256>>>((const float4*)a_in_e, (const float4*)a_out_e,
                         (const float4*)txt_e, tot_in, (float4*)out);
    k_meta<<<(BM_ + 255) / 256, 256>>>(ids, labels, amask, tot_in, out);
    k_pos<<<B_, 256>>>(out);
}